// round 1
// baseline (speedup 1.0000x reference)
#include <cuda_runtime.h>
#include <math_constants.h>

// Problem constants
#define NROWS 16384   // B*H*W = 16*32*32
#define NE    8192    // codebook entries
#define EDIM  256     // embedding dim (== C)
#define CH    256
#define HWSZ  1024    // H*W
#define ZQ_ELEMS 4194304            // 16*256*32*32
#define LOSS_OFF 4194304
#define IDX_OFF  4194305

// Scratch (no allocations allowed -> __device__ globals)
__device__ float g_zz[NROWS];
__device__ float g_ee[NE];
__device__ int   g_idx[NROWS];
__device__ double g_loss;

// ---------------------------------------------------------------------------
// prep: zz[n] = sum_c z[b,c,h,w]^2 (unfused mul+add, sequential order to mimic
// the reference's z*z followed by sum), ee[k] = sum_d cb[k,d]^2, zero loss.
// ---------------------------------------------------------------------------
__global__ void prep_kernel(const float* __restrict__ z,
                            const float* __restrict__ cb) {
    int t = blockIdx.x * blockDim.x + threadIdx.x;
    if (t == 0) g_loss = 0.0;
    if (t < NROWS) {
        int b = t >> 10;
        int hw = t & 1023;
        const float* p = z + (size_t)b * CH * HWSZ + hw;
        float s = 0.0f;
#pragma unroll 8
        for (int c = 0; c < CH; c++) {
            float v = p[c * HWSZ];
            s = __fadd_rn(s, __fmul_rn(v, v));   // no FMA fusion: match ref rounding
        }
        g_zz[t] = s;
    } else if (t < NROWS + NE) {
        int k = t - NROWS;
        const float* p = cb + (size_t)k * EDIM;
        float s = 0.0f;
#pragma unroll 8
        for (int d = 0; d < EDIM; d++) {
            float v = p[d];
            s = __fadd_rn(s, __fmul_rn(v, v));
        }
        g_ee[k] = s;
    }
}

// ---------------------------------------------------------------------------
// argmin GEMM: for each row n, argmin_k fl( fl(zz[n]+ee[k]) - fl(2*z_n.e_k) )
// Tiling: BM=128 rows x BN=128 cands per block, D in chunks of 32.
// 256 threads, 8x8 register tile each. Ties -> smallest k (first index).
// ---------------------------------------------------------------------------
#define BM 128
#define BN 128
#define BD 32
#define BS_STRIDE 132   // padded to kill bank conflicts, multiple of 4 for float4

__global__ __launch_bounds__(256, 1)
void vq_argmin_kernel(const float* __restrict__ z,
                      const float* __restrict__ cb) {
    __shared__ float As[BD][BM];          // A-tile, [d][row]
    __shared__ float Bs[BD][BS_STRIDE];   // B-tile, [d][cand]

    const int tid = threadIdx.x;
    const int tx = tid & 15;          // candidate group (8 cands each)
    const int ty = tid >> 4;          // row group (8 rows each)

    const int rowTile = blockIdx.x;   // 0..127
    const int b   = rowTile >> 3;     // 8 tiles of 128 rows per batch image
    const int hw0 = (rowTile & 7) << 7;
    const float* zbase = z + (size_t)b * CH * HWSZ + hw0;

    float rmin[8];
    int   ridx[8];
    float rzz[8];
#pragma unroll
    for (int i = 0; i < 8; i++) {
        rmin[i] = CUDART_INF_F;
        ridx[i] = 0;
        rzz[i]  = g_zz[rowTile * BM + ty * 8 + i];
    }

    float acc[8][8];

    for (int kb = 0; kb < NE; kb += BN) {
#pragma unroll
        for (int i = 0; i < 8; i++)
#pragma unroll
            for (int j = 0; j < 8; j++) acc[i][j] = 0.0f;

        for (int dc = 0; dc < EDIM; dc += BD) {
            __syncthreads();   // previous compute done before overwriting tiles
            // ---- load A tile: z[b, dc+d, hw0 + r], coalesced float4 over rows
            {
                int r4 = tid & 31;        // 32 float4 groups cover 128 rows
                int d0 = tid >> 5;        // 8 d-slots per pass
#pragma unroll
                for (int it = 0; it < 4; it++) {
                    int d = d0 + (it << 3);
                    float4 v = *(const float4*)(zbase + (size_t)(dc + d) * HWSZ + (r4 << 2));
                    *(float4*)&As[d][r4 << 2] = v;
                }
            }
            // ---- load B tile: cb[kb+k, dc+dvec*4..+3], transpose into Bs[d][k]
            {
                int dvec = tid & 7;       // 8 float4 groups cover 32 d
                int k0 = tid >> 3;        // 32 cands per pass
#pragma unroll
                for (int it = 0; it < 4; it++) {
                    int k = k0 + (it << 5);
                    float4 v = *(const float4*)(cb + (size_t)(kb + k) * EDIM + dc + (dvec << 2));
                    Bs[dvec * 4 + 0][k] = v.x;
                    Bs[dvec * 4 + 1][k] = v.y;
                    Bs[dvec * 4 + 2][k] = v.z;
                    Bs[dvec * 4 + 3][k] = v.w;
                }
            }
            __syncthreads();
            // ---- 8x8 FFMA microkernel
#pragma unroll
            for (int d = 0; d < BD; d++) {
                float a[8], bv[8];
                *(float4*)(&a[0])  = *(const float4*)(&As[d][ty * 8]);
                *(float4*)(&a[4])  = *(const float4*)(&As[d][ty * 8 + 4]);
                *(float4*)(&bv[0]) = *(const float4*)(&Bs[d][tx * 8]);
                *(float4*)(&bv[4]) = *(const float4*)(&Bs[d][tx * 8 + 4]);
#pragma unroll
                for (int i = 0; i < 8; i++)
#pragma unroll
                    for (int j = 0; j < 8; j++)
                        acc[i][j] = fmaf(a[i], bv[j], acc[i][j]);
            }
        }

        // ---- epilogue: reference-rounding distance + running argmin
#pragma unroll
        for (int j = 0; j < 8; j++) {
            int k = kb + tx * 8 + j;           // ascending k within thread
            float eek = g_ee[k];
#pragma unroll
            for (int i = 0; i < 8; i++) {
                float t    = __fadd_rn(rzz[i], eek);          // fl(zz+ee)
                float dval = __fadd_rn(t, -2.0f * acc[i][j]); // fl(t - 2*ze), 2*ze exact
                if (dval < rmin[i]) { rmin[i] = dval; ridx[i] = k; }  // strict: first index wins
            }
        }
    }

    // ---- cross-thread reduction (16 partials per row), reuse smem
    __syncthreads();
    float* Rv = &As[0][0];        // 128*16 floats
    int*   Ri = (int*)&Bs[0][0];  // 128*16 ints
#pragma unroll
    for (int i = 0; i < 8; i++) {
        int r = ty * 8 + i;
        Rv[r * 16 + tx] = rmin[i];
        Ri[r * 16 + tx] = ridx[i];
    }
    __syncthreads();
    if (tid < BM) {
        float bv = Rv[tid * 16];
        int   bi = Ri[tid * 16];
#pragma unroll
        for (int t = 1; t < 16; t++) {
            float v = Rv[tid * 16 + t];
            int   ii = Ri[tid * 16 + t];
            if (v < bv || (v == bv && ii < bi)) { bv = v; bi = ii; }
        }
        g_idx[rowTile * BM + tid] = bi;
    }
}

// ---------------------------------------------------------------------------
// output: z_q gather (NCHW layout, coalesced writes) + loss partial sums
// ---------------------------------------------------------------------------
__global__ void output_kernel(const float* __restrict__ z,
                              const float* __restrict__ cb,
                              float* __restrict__ out) {
    float lsum = 0.0f;
    int stride = gridDim.x * blockDim.x;
    for (int o = blockIdx.x * blockDim.x + threadIdx.x; o < ZQ_ELEMS; o += stride) {
        int bq = o >> 18;
        int c  = (o >> 10) & 255;
        int hw = o & 1023;
        int n  = (bq << 10) | hw;
        int id = g_idx[n];
        float q  = __ldg(&cb[(size_t)id * EDIM + c]);
        float zp = z[o];
        out[o] = q;
        float dd = q - zp;
        lsum += dd * dd;
    }
    // block reduce
    __shared__ float red[256];
    red[threadIdx.x] = lsum;
    __syncthreads();
    for (int s = 128; s > 0; s >>= 1) {
        if (threadIdx.x < s) red[threadIdx.x] += red[threadIdx.x + s];
        __syncthreads();
    }
    if (threadIdx.x == 0) atomicAdd(&g_loss, (double)red[0]);
}

// ---------------------------------------------------------------------------
// finalize: loss scalar (mean is /2^22 -> exact scaling) + idx as floats
// ---------------------------------------------------------------------------
__global__ void finalize_kernel(float* __restrict__ out, int out_size) {
    int t = blockIdx.x * blockDim.x + threadIdx.x;
    if (t == 0 && out_size > LOSS_OFF) {
        float m = (float)(g_loss * (1.0 / 4194304.0));
        out[LOSS_OFF] = __fadd_rn(m, 0.25f * m);   // m + beta*m, ref rounding
    }
    if (t < NROWS && out_size >= IDX_OFF + NROWS) {
        out[IDX_OFF + t] = (float)g_idx[t];
    }
}

// ---------------------------------------------------------------------------
extern "C" void kernel_launch(void* const* d_in, const int* in_sizes, int n_in,
                              void* d_out, int out_size) {
    const float* z  = (const float*)d_in[0];
    const float* cb = (const float*)d_in[1];
    float* out = (float*)d_out;

    prep_kernel<<<(NROWS + NE + 255) / 256, 256>>>(z, cb);
    vq_argmin_kernel<<<NROWS / BM, 256>>>(z, cb);
    output_kernel<<<1024, 256>>>(z, cb, out);
    finalize_kernel<<<(NROWS + 255) / 256, 256>>>(out, out_size);
}

// round 2
// speedup vs baseline: 1.2804x; 1.2804x over previous
#include <cuda_runtime.h>
#include <math_constants.h>

// Problem constants
#define NROWS 16384   // B*H*W = 16*32*32
#define NE    8192    // codebook entries
#define EDIM  256     // embedding dim (== C)
#define CH    256
#define HWSZ  1024    // H*W
#define ZQ_ELEMS 4194304            // 16*256*32*32
#define LOSS_OFF 4194304
#define IDX_OFF  4194305

#define NCHUNK 8          // NE split into 8 chunks of 1024 cands -> 1024 tasks
#define CANDS_PER_CHUNK 1024

// Scratch (no allocations allowed -> __device__ globals)
__device__ float g_zz[NROWS];
__device__ float g_ee[NE];
__device__ int   g_idx[NROWS];
__device__ float g_pval[NCHUNK * NROWS];
__device__ int   g_pidx[NCHUNK * NROWS];
__device__ double g_loss;

// ---------------------------------------------------------------------------
// prep: zz[n] = sum_c z[b,c,h,w]^2 (unfused mul+add, sequential order to mimic
// the reference rounding), ee[k] = sum_d cb[k,d]^2, zero loss.
// ---------------------------------------------------------------------------
__global__ void prep_kernel(const float* __restrict__ z,
                            const float* __restrict__ cb) {
    int t = blockIdx.x * blockDim.x + threadIdx.x;
    if (t == 0) g_loss = 0.0;
    if (t < NROWS) {
        int b = t >> 10;
        int hw = t & 1023;
        const float* p = z + (size_t)b * CH * HWSZ + hw;
        float s = 0.0f;
#pragma unroll 8
        for (int c = 0; c < CH; c++) {
            float v = p[c * HWSZ];
            s = __fadd_rn(s, __fmul_rn(v, v));   // no FMA fusion: match ref rounding
        }
        g_zz[t] = s;
    } else if (t < NROWS + NE) {
        int k = t - NROWS;
        const float* p = cb + (size_t)k * EDIM;
        float s = 0.0f;
#pragma unroll 8
        for (int d = 0; d < EDIM; d++) {
            float v = p[d];
            s = __fadd_rn(s, __fmul_rn(v, v));
        }
        g_ee[k] = s;
    }
}

// ---------------------------------------------------------------------------
// argmin GEMM, task = (rowTile, chunk). 1024 tasks of 128 rows x 1024 cands.
// BM=128 rows, BN=128 cands per kb iter, D chunks of BD=16, double-buffered
// through registers. 256 threads, 8x8 register tile
// (cands split as tx*4+j and 64+tx*4+j for conflict-free smem reads).
// Distance rounding replicates the reference: fl(fl(zz+ee) - fl(2*z.e)).
// Ties -> smallest k.
// ---------------------------------------------------------------------------
#define BM 128
#define BN 128
#define BD 16
#define BS_STRIDE 132

__global__ __launch_bounds__(256)
void vq_argmin_kernel(const float* __restrict__ z,
                      const float* __restrict__ cb) {
    __shared__ float As[2][BD][BM];          // [buf][d][row]
    __shared__ float Bs[2][BD][BS_STRIDE];   // [buf][d][cand]

    const int tid = threadIdx.x;
    const int tx = tid & 15;          // candidate group
    const int ty = tid >> 4;          // row group (8 rows each)

    const int task    = blockIdx.x;   // 0..1023
    const int rowTile = task >> 3;    // 0..127
    const int chunk   = task & 7;     // candidate chunk

    const int b   = rowTile >> 3;
    const int hw0 = (rowTile & 7) << 7;
    const float* zbase = z + (size_t)b * CH * HWSZ + hw0;

    // load indices (A tile)
    const int a_r4 = tid & 31;        // float4 group over rows
    const int a_d0 = tid >> 5;        // d slot (+0, +8)
    // load indices (B tile)
    const int b_dv = tid & 3;         // d float4 group
    const int b_k0 = tid >> 2;        // cand row (+0, +64)

    float rmin[8];
    int   ridx[8];
    float rzz[8];
#pragma unroll
    for (int i = 0; i < 8; i++) {
        rmin[i] = CUDART_INF_F;
        ridx[i] = 0;
        rzz[i]  = g_zz[rowTile * BM + ty * 8 + i];
    }

    float acc[8][8];

    for (int kbi = 0; kbi < CANDS_PER_CHUNK / BN; kbi++) {
        const int kb = chunk * CANDS_PER_CHUNK + kbi * BN;
        const float* cbbase = cb + (size_t)kb * EDIM;

#pragma unroll
        for (int i = 0; i < 8; i++)
#pragma unroll
            for (int j = 0; j < 8; j++) acc[i][j] = 0.0f;

        // ---- prologue: load dc=0 tile into buffer 0
        float4 rA[2], rB[2];
#pragma unroll
        for (int it = 0; it < 2; it++) {
            int d = a_d0 + it * 8;
            rA[it] = *(const float4*)(zbase + (size_t)d * HWSZ + (a_r4 << 2));
            int k = b_k0 + it * 64;
            rB[it] = *(const float4*)(cbbase + (size_t)k * EDIM + (b_dv << 2));
        }
#pragma unroll
        for (int it = 0; it < 2; it++) {
            int d = a_d0 + it * 8;
            *(float4*)&As[0][d][a_r4 << 2] = rA[it];
            int k = b_k0 + it * 64;
            Bs[0][b_dv * 4 + 0][k] = rB[it].x;
            Bs[0][b_dv * 4 + 1][k] = rB[it].y;
            Bs[0][b_dv * 4 + 2][k] = rB[it].z;
            Bs[0][b_dv * 4 + 3][k] = rB[it].w;
        }
        __syncthreads();

        int cur = 0;
#pragma unroll 1
        for (int dci = 0; dci < EDIM / BD; dci++) {
            const int dcn = (dci + 1) * BD;   // next chunk base
            const bool has_next = (dci + 1 < EDIM / BD);
            // ---- issue global loads for next tile (latency hidden by compute)
            if (has_next) {
#pragma unroll
                for (int it = 0; it < 2; it++) {
                    int d = dcn + a_d0 + it * 8;
                    rA[it] = *(const float4*)(zbase + (size_t)d * HWSZ + (a_r4 << 2));
                    int k = b_k0 + it * 64;
                    rB[it] = *(const float4*)(cbbase + (size_t)k * EDIM + dcn + (b_dv << 2));
                }
            }
            // ---- compute on current buffer
#pragma unroll
            for (int d = 0; d < BD; d++) {
                float a[8], bv[8];
                *(float4*)(&a[0])  = *(const float4*)(&As[cur][d][ty * 8]);
                *(float4*)(&a[4])  = *(const float4*)(&As[cur][d][ty * 8 + 4]);
                *(float4*)(&bv[0]) = *(const float4*)(&Bs[cur][d][tx * 4]);
                *(float4*)(&bv[4]) = *(const float4*)(&Bs[cur][d][64 + tx * 4]);
#pragma unroll
                for (int i = 0; i < 8; i++)
#pragma unroll
                    for (int j = 0; j < 8; j++)
                        acc[i][j] = fmaf(a[i], bv[j], acc[i][j]);
            }
            // ---- fill the other buffer, one barrier per iteration
            if (has_next) {
                int nxt = cur ^ 1;
#pragma unroll
                for (int it = 0; it < 2; it++) {
                    int d = a_d0 + it * 8;
                    *(float4*)&As[nxt][d][a_r4 << 2] = rA[it];
                    int k = b_k0 + it * 64;
                    Bs[nxt][b_dv * 4 + 0][k] = rB[it].x;
                    Bs[nxt][b_dv * 4 + 1][k] = rB[it].y;
                    Bs[nxt][b_dv * 4 + 2][k] = rB[it].z;
                    Bs[nxt][b_dv * 4 + 3][k] = rB[it].w;
                }
                __syncthreads();
                cur = nxt;
            }
        }

        // ---- epilogue: reference-rounding distance + running argmin
        //      j=0..3 -> cand tx*4+j ; j=4..7 -> cand 64+tx*4+(j-4) (ascending)
#pragma unroll
        for (int j = 0; j < 8; j++) {
            int k = kb + ((j < 4) ? (tx * 4 + j) : (64 + tx * 4 + j - 4));
            float eek = g_ee[k];
#pragma unroll
            for (int i = 0; i < 8; i++) {
                float t    = __fadd_rn(rzz[i], eek);          // fl(zz+ee)
                float dval = __fadd_rn(t, -2.0f * acc[i][j]); // fl(t - 2*ze)
                if (dval < rmin[i]) { rmin[i] = dval; ridx[i] = k; }
            }
        }
        __syncthreads();   // before tiles are overwritten by next kb prologue
    }

    // ---- cross-thread reduction (16 partials per row), reuse smem
    float* Rv = &As[0][0][0];        // 128*16 floats = 8KB
    int*   Ri = (int*)&Bs[0][0][0];
#pragma unroll
    for (int i = 0; i < 8; i++) {
        int r = ty * 8 + i;
        Rv[r * 16 + tx] = rmin[i];
        Ri[r * 16 + tx] = ridx[i];
    }
    __syncthreads();
    if (tid < BM) {
        float bv = Rv[tid * 16];
        int   bi = Ri[tid * 16];
#pragma unroll
        for (int t = 1; t < 16; t++) {
            float v = Rv[tid * 16 + t];
            int   ii = Ri[tid * 16 + t];
            if (v < bv || (v == bv && ii < bi)) { bv = v; bi = ii; }
        }
        g_pval[chunk * NROWS + rowTile * BM + tid] = bv;
        g_pidx[chunk * NROWS + rowTile * BM + tid] = bi;
    }
}

// ---------------------------------------------------------------------------
// combine: merge the NCHUNK partials per row. Chunks scanned in ascending-k
// order with strict < -> identical tie behavior to a monolithic scan.
// ---------------------------------------------------------------------------
__global__ void combine_kernel() {
    int n = blockIdx.x * blockDim.x + threadIdx.x;
    if (n < NROWS) {
        float bv = g_pval[n];
        int   bi = g_pidx[n];
#pragma unroll
        for (int c = 1; c < NCHUNK; c++) {
            float v = g_pval[c * NROWS + n];
            int   ii = g_pidx[c * NROWS + n];
            if (v < bv) { bv = v; bi = ii; }
        }
        g_idx[n] = bi;
    }
}

// ---------------------------------------------------------------------------
// output: z_q gather (NCHW layout, coalesced writes) + loss partial sums
// ---------------------------------------------------------------------------
__global__ void output_kernel(const float* __restrict__ z,
                              const float* __restrict__ cb,
                              float* __restrict__ out) {
    float lsum = 0.0f;
    int stride = gridDim.x * blockDim.x;
    for (int o = blockIdx.x * blockDim.x + threadIdx.x; o < ZQ_ELEMS; o += stride) {
        int bq = o >> 18;
        int c  = (o >> 10) & 255;
        int hw = o & 1023;
        int n  = (bq << 10) | hw;
        int id = g_idx[n];
        float q  = __ldg(&cb[(size_t)id * EDIM + c]);
        float zp = z[o];
        out[o] = q;
        float dd = q - zp;
        lsum += dd * dd;
    }
    __shared__ float red[256];
    red[threadIdx.x] = lsum;
    __syncthreads();
    for (int s = 128; s > 0; s >>= 1) {
        if (threadIdx.x < s) red[threadIdx.x] += red[threadIdx.x + s];
        __syncthreads();
    }
    if (threadIdx.x == 0) atomicAdd(&g_loss, (double)red[0]);
}

// ---------------------------------------------------------------------------
// finalize: loss scalar (mean is /2^22 -> exact scaling) + idx as floats
// ---------------------------------------------------------------------------
__global__ void finalize_kernel(float* __restrict__ out, int out_size) {
    int t = blockIdx.x * blockDim.x + threadIdx.x;
    if (t == 0 && out_size > LOSS_OFF) {
        float m = (float)(g_loss * (1.0 / 4194304.0));
        out[LOSS_OFF] = __fadd_rn(m, 0.25f * m);   // m + beta*m
    }
    if (t < NROWS && out_size >= IDX_OFF + NROWS) {
        out[IDX_OFF + t] = (float)g_idx[t];
    }
}

// ---------------------------------------------------------------------------
extern "C" void kernel_launch(void* const* d_in, const int* in_sizes, int n_in,
                              void* d_out, int out_size) {
    const float* z  = (const float*)d_in[0];
    const float* cb = (const float*)d_in[1];
    float* out = (float*)d_out;

    prep_kernel<<<(NROWS + NE + 255) / 256, 256>>>(z, cb);
    vq_argmin_kernel<<<NROWS / BM * NCHUNK, 256>>>(z, cb);
    combine_kernel<<<(NROWS + 255) / 256, 256>>>();
    output_kernel<<<1024, 256>>>(z, cb, out);
    finalize_kernel<<<(NROWS + 255) / 256, 256>>>(out, out_size);
}

// round 4
// speedup vs baseline: 3.6516x; 2.8519x over previous
#include <cuda_runtime.h>
#include <cuda_fp16.h>
#include <cuda_bf16.h>
#include <math_constants.h>
#include <cstdint>

// ---------------------------------------------------------------- constants
#define NROWS 16384   // B*H*W
#define NE    8192
#define EDIM  256
#define CH    256
#define HWSZ  1024
#define ZQ_ELEMS 4194304
#define LOSS_OFF 4194304
#define IDX_OFF  4194305
#define CAP   32      // shortlist capacity per row

// ---------------------------------------------------------------- scratch
__device__ float    g_zz[NROWS];
__device__ float    g_ee[NE];
__device__ int      g_idx[NROWS];
__device__ double   g_loss;
__device__ unsigned g_maxee;
__device__ unsigned g_rowmin[NROWS];        // order-mapped float
__device__ int      g_ccount[NROWS];
__device__ int      g_clist[NROWS][CAP];
__device__ float    g_Azf[NROWS * EDIM];    // z transposed, fp32 (for rescore)
__device__ uint16_t g_Abf[NROWS * EDIM];    // z transposed, bf16
__device__ uint16_t g_Bbf[NE * EDIM];       // codebook, bf16
__device__ uint16_t g_score[(size_t)NROWS * NE];  // fp16 scores, 256MB

// order-preserving float<->uint map (for atomicMin on floats of any sign)
__device__ __forceinline__ unsigned fmap(float f) {
    unsigned u = __float_as_uint(f);
    return (u & 0x80000000u) ? ~u : (u | 0x80000000u);
}
__device__ __forceinline__ float funmap(unsigned u) {
    u = (u & 0x80000000u) ? (u & 0x7FFFFFFFu) : ~u;
    return __uint_as_float(u);
}

// ---------------------------------------------------------------------------
__global__ void init_kernel() { g_maxee = 0; g_loss = 0.0; }

// prep: zz (ref rounding: unfused mul+add, ascending), ee (+ maxee),
//       reset rowmin/ccount
__global__ void prep_kernel(const float* __restrict__ z,
                            const float* __restrict__ cb) {
    int t = blockIdx.x * blockDim.x + threadIdx.x;
    if (t < NROWS) {
        g_rowmin[t] = 0xFFFFFFFFu;
        g_ccount[t] = 0;
        int b = t >> 10, hw = t & 1023;
        const float* p = z + (size_t)b * CH * HWSZ + hw;
        float s = 0.0f;
#pragma unroll 8
        for (int c = 0; c < CH; c++) {
            float v = p[c * HWSZ];
            s = __fadd_rn(s, __fmul_rn(v, v));
        }
        g_zz[t] = s;
    } else if (t < NROWS + NE) {
        int k = t - NROWS;
        const float* p = cb + (size_t)k * EDIM;
        float s = 0.0f;
#pragma unroll 8
        for (int d = 0; d < EDIM; d++) {
            float v = p[d];
            s = __fadd_rn(s, __fmul_rn(v, v));
        }
        g_ee[k] = s;
        atomicMax(&g_maxee, __float_as_uint(s));   // s >= 0: uint order ok
    }
}

// codebook -> bf16
__global__ void split_cb_kernel(const float* __restrict__ cb) {
    int i = blockIdx.x * blockDim.x + threadIdx.x;
    if (i < NE * EDIM) {
        __nv_bfloat16 h = __float2bfloat16_rn(cb[i]);
        g_Bbf[i] = *(uint16_t*)&h;
    }
}

// z: NCHW -> row-major [NROWS][EDIM], fp32 + bf16
__global__ void split_z_kernel(const float* __restrict__ z) {
    __shared__ float s[32][33];
    int b = blockIdx.z, c0 = blockIdx.y * 32, hw0 = blockIdx.x * 32;
    int tx = threadIdx.x, ty = threadIdx.y;   // block (32, 8)
    const float* zp = z + ((size_t)b * CH + c0) * HWSZ + hw0;
#pragma unroll
    for (int i = 0; i < 4; i++) {
        int cl = ty + i * 8;
        s[cl][tx] = zp[(size_t)cl * HWSZ + tx];
    }
    __syncthreads();
#pragma unroll
    for (int i = 0; i < 4; i++) {
        int hl = ty + i * 8;
        size_t o = (size_t)(b * HWSZ + hw0 + hl) * EDIM + c0 + tx;
        float x = s[tx][hl];
        g_Azf[o] = x;
        __nv_bfloat16 h = __float2bfloat16_rn(x);
        g_Abf[o] = *(uint16_t*)&h;
    }
}

// ---------------------------------------------------------------------------
// screening GEMM: bf16 mma.sync, CTA tile 128 rows x 128 cands, K=256.
// 8 warps as (wm 0..3) x (wn 0..1): warp tile 32x64, mma m16n8k16.
// Emits fp16 score s = ee - 2*dot and per-row running min (atomics).
// ---------------------------------------------------------------------------
__global__ void __launch_bounds__(256) screen_kernel() {
    __shared__ __align__(16) uint8_t sA[2][8192];   // 128 rows x 32 bf16
    __shared__ __align__(16) uint8_t sB[2][8192];
    __shared__ unsigned s_rmin[128];

    const int tid = threadIdx.x, lane = tid & 31, wid = tid >> 5;
    const int candTile = blockIdx.x & 63;
    const int rowTile  = blockIdx.x >> 6;
    const int row0 = rowTile * 128, cand0 = candTile * 128;
    const int wm = wid & 3, wn = wid >> 2;
    const int g = lane >> 2, tg = lane & 3;

    if (tid < 128) s_rmin[tid] = 0xFFFFFFFFu;

    float acc[2][8][4];
#pragma unroll
    for (int mf = 0; mf < 2; mf++)
#pragma unroll
        for (int nf = 0; nf < 8; nf++)
#pragma unroll
            for (int q = 0; q < 4; q++) acc[mf][nf][q] = 0.0f;

    uint4 pa[2], pb[2];

#define LDG_CHUNK(kc)                                                          \
    {                                                                          \
        _Pragma("unroll")                                                      \
        for (int it = 0; it < 2; it++) {                                       \
            int u = tid + it * 256, r = u >> 2, c = u & 3;                     \
            pa[it] = *(const uint4*)(g_Abf + (size_t)(row0 + r) * EDIM + (kc) * 32 + c * 8);  \
            pb[it] = *(const uint4*)(g_Bbf + (size_t)(cand0 + r) * EDIM + (kc) * 32 + c * 8); \
        }                                                                      \
    }
#define STS_CHUNK(buf)                                                         \
    {                                                                          \
        _Pragma("unroll")                                                      \
        for (int it = 0; it < 2; it++) {                                       \
            int u = tid + it * 256, r = u >> 2, c = u & 3;                     \
            int cs = c ^ ((r >> 1) & 3);                                       \
            *(uint4*)(sA[buf] + r * 64 + cs * 16) = pa[it];                    \
            *(uint4*)(sB[buf] + r * 64 + cs * 16) = pb[it];                    \
        }                                                                      \
    }

    LDG_CHUNK(0);
    STS_CHUNK(0);
    __syncthreads();

#pragma unroll 1
    for (int kc = 0; kc < 8; kc++) {
        if (kc < 7) LDG_CHUNK(kc + 1);
        const int buf = kc & 1;
#pragma unroll
        for (int s2 = 0; s2 < 2; s2++) {
            const int c0 = s2 * 2, c1 = c0 + 1;
            uint32_t a[2][4], b[8][2];
#pragma unroll
            for (int mf = 0; mf < 2; mf++) {
                int r  = wm * 32 + mf * 16 + g;
                int r8 = r + 8;
                a[mf][0] = *(const uint32_t*)(sA[buf] + r  * 64 + ((c0 ^ ((r  >> 1) & 3)) * 16) + tg * 4);
                a[mf][1] = *(const uint32_t*)(sA[buf] + r8 * 64 + ((c0 ^ ((r8 >> 1) & 3)) * 16) + tg * 4);
                a[mf][2] = *(const uint32_t*)(sA[buf] + r  * 64 + ((c1 ^ ((r  >> 1) & 3)) * 16) + tg * 4);
                a[mf][3] = *(const uint32_t*)(sA[buf] + r8 * 64 + ((c1 ^ ((r8 >> 1) & 3)) * 16) + tg * 4);
            }
#pragma unroll
            for (int nf = 0; nf < 8; nf++) {
                int r = wn * 64 + nf * 8 + g;
                b[nf][0] = *(const uint32_t*)(sB[buf] + r * 64 + ((c0 ^ ((r >> 1) & 3)) * 16) + tg * 4);
                b[nf][1] = *(const uint32_t*)(sB[buf] + r * 64 + ((c1 ^ ((r >> 1) & 3)) * 16) + tg * 4);
            }
#pragma unroll
            for (int mf = 0; mf < 2; mf++)
#pragma unroll
                for (int nf = 0; nf < 8; nf++)
                    asm volatile(
                        "mma.sync.aligned.m16n8k16.row.col.f32.bf16.bf16.f32 "
                        "{%0,%1,%2,%3},{%4,%5,%6,%7},{%8,%9},{%0,%1,%2,%3};"
                        : "+f"(acc[mf][nf][0]), "+f"(acc[mf][nf][1]),
                          "+f"(acc[mf][nf][2]), "+f"(acc[mf][nf][3])
                        : "r"(a[mf][0]), "r"(a[mf][1]), "r"(a[mf][2]), "r"(a[mf][3]),
                          "r"(b[nf][0]), "r"(b[nf][1]));
        }
        if (kc < 7) {
            STS_CHUNK((kc + 1) & 1);
            __syncthreads();
        }
    }

    // epilogue: scores + per-row min
#pragma unroll
    for (int mf = 0; mf < 2; mf++)
#pragma unroll
        for (int h = 0; h < 2; h++) {
            int rl = wm * 32 + mf * 16 + g + h * 8;
            int row = row0 + rl;
            float rmin = CUDART_INF_F;
#pragma unroll
            for (int nf = 0; nf < 8; nf++) {
                int cand = cand0 + wn * 64 + nf * 8 + 2 * tg;
                float s0 = __ldg(&g_ee[cand])     - 2.0f * acc[mf][nf][h * 2 + 0];
                float s1 = __ldg(&g_ee[cand + 1]) - 2.0f * acc[mf][nf][h * 2 + 1];
                __half2 hv = __floats2half2_rn(s0, s1);
                *(uint32_t*)&g_score[(size_t)row * NE + cand] = *(uint32_t*)&hv;
                rmin = fminf(rmin, fminf(s0, s1));
            }
            atomicMin(&s_rmin[rl], fmap(rmin));
        }
    __syncthreads();
    if (tid < 128) atomicMin(&g_rowmin[row0 + tid], s_rmin[tid]);
}

// ---------------------------------------------------------------------------
// collect: one warp per row, gather candidates with score <= min + margin.
// margin >= 2*eps_screen (deterministic Cauchy-Schwarz bound) + fp16 slack.
// ---------------------------------------------------------------------------
__global__ void collect_kernel() {
    int w = (blockIdx.x * blockDim.x + threadIdx.x) >> 5;
    int lane = threadIdx.x & 31;
    if (w >= NROWS) return;
    float fmin = funmap(g_rowmin[w]);
    float marg = 0.024f * sqrtf(g_zz[w]) * sqrtf(__uint_as_float(g_maxee)) + 2e-5f;
    float thr = fmin + marg;
    const uint16_t* sp = g_score + (size_t)w * NE;
#pragma unroll 1
    for (int it = 0; it < 32; it++) {
        int cb0 = it * 256 + lane * 8;
        uint4 v = *(const uint4*)(sp + cb0);
        const __half2* hp = (const __half2*)&v;
#pragma unroll
        for (int q = 0; q < 4; q++) {
            float2 f2 = __half22float2(hp[q]);
            if (f2.x <= thr) {
                int p = atomicAdd(&g_ccount[w], 1);
                if (p < CAP) g_clist[w][p] = cb0 + q * 2;
            }
            if (f2.y <= thr) {
                int p = atomicAdd(&g_ccount[w], 1);
                if (p < CAP) g_clist[w][p] = cb0 + q * 2 + 1;
            }
        }
    }
}

// ---------------------------------------------------------------------------
// rescore: exact fp32 (ascending-d fmaf chain == R2) + reference rounding,
// lexicographic (d, idx) min -> first-index tie behavior. Warp per row.
// ---------------------------------------------------------------------------
__global__ void rescore_kernel(const float* __restrict__ cb) {
    int w = (blockIdx.x * blockDim.x + threadIdx.x) >> 5;
    int lane = threadIdx.x & 31;
    if (w >= NROWS) return;
    int cnt = g_ccount[w];
    float zzv = g_zz[w];
    const float* zr = g_Azf + (size_t)w * EDIM;
    float bd = CUDART_INF_F;
    int bi = 0x7FFFFFFF;
    if (cnt <= CAP) {
        if (lane < cnt) {
            int k = g_clist[w][lane];
            const float* er = cb + (size_t)k * EDIM;
            float s = 0.0f;
#pragma unroll 8
            for (int d = 0; d < EDIM; d++) s = fmaf(zr[d], er[d], s);
            float t = __fadd_rn(zzv, g_ee[k]);
            bd = __fadd_rn(t, -2.0f * s);
            bi = k;
        }
    } else {  // overflow (vanishingly rare): exact scan of all candidates
        for (int k = lane; k < NE; k += 32) {
            const float* er = cb + (size_t)k * EDIM;
            float s = 0.0f;
#pragma unroll 8
            for (int d = 0; d < EDIM; d++) s = fmaf(zr[d], er[d], s);
            float t = __fadd_rn(zzv, g_ee[k]);
            float dv = __fadd_rn(t, -2.0f * s);
            if (dv < bd || (dv == bd && k < bi)) { bd = dv; bi = k; }
        }
    }
#pragma unroll
    for (int o = 16; o; o >>= 1) {
        float od = __shfl_xor_sync(0xFFFFFFFFu, bd, o);
        int   oi = __shfl_xor_sync(0xFFFFFFFFu, bi, o);
        if (od < bd || (od == bd && oi < bi)) { bd = od; bi = oi; }
    }
    if (lane == 0) g_idx[w] = bi;
}

// ---------------------------------------------------------------------------
// output: z_q gather + loss partial sums
// ---------------------------------------------------------------------------
__global__ void output_kernel(const float* __restrict__ z,
                              const float* __restrict__ cb,
                              float* __restrict__ out) {
    float lsum = 0.0f;
    int stride = gridDim.x * blockDim.x;
    for (int o = blockIdx.x * blockDim.x + threadIdx.x; o < ZQ_ELEMS; o += stride) {
        int bq = o >> 18;
        int c  = (o >> 10) & 255;
        int hw = o & 1023;
        int n  = (bq << 10) | hw;
        int id = g_idx[n];
        float q  = __ldg(&cb[(size_t)id * EDIM + c]);
        float zp = z[o];
        out[o] = q;
        float dd = q - zp;
        lsum += dd * dd;
    }
    __shared__ float red[256];
    red[threadIdx.x] = lsum;
    __syncthreads();
    for (int s = 128; s > 0; s >>= 1) {
        if (threadIdx.x < s) red[threadIdx.x] += red[threadIdx.x + s];
        __syncthreads();
    }
    if (threadIdx.x == 0) atomicAdd(&g_loss, (double)red[0]);
}

__global__ void finalize_kernel(float* __restrict__ out, int out_size) {
    int t = blockIdx.x * blockDim.x + threadIdx.x;
    if (t == 0 && out_size > LOSS_OFF) {
        float m = (float)(g_loss * (1.0 / 4194304.0));
        out[LOSS_OFF] = __fadd_rn(m, 0.25f * m);
    }
    if (t < NROWS && out_size >= IDX_OFF + NROWS) {
        out[IDX_OFF + t] = (float)g_idx[t];
    }
}

// ---------------------------------------------------------------------------
extern "C" void kernel_launch(void* const* d_in, const int* in_sizes, int n_in,
                              void* d_out, int out_size) {
    const float* z  = (const float*)d_in[0];
    const float* cb = (const float*)d_in[1];
    float* out = (float*)d_out;

    init_kernel<<<1, 1>>>();
    prep_kernel<<<(NROWS + NE + 255) / 256, 256>>>(z, cb);
    split_cb_kernel<<<(NE * EDIM) / 256, 256>>>(cb);
    split_z_kernel<<<dim3(HWSZ / 32, CH / 32, 16), dim3(32, 8)>>>(z);
    screen_kernel<<<128 * 64, 256>>>();
    collect_kernel<<<(NROWS * 32) / 256, 256>>>();
    rescore_kernel<<<(NROWS * 32) / 256, 256>>>(cb);
    output_kernel<<<1024, 256>>>(z, cb, out);
    finalize_kernel<<<(NROWS + 255) / 256, 256>>>(out, out_size);
}

// round 6
// speedup vs baseline: 3.7524x; 1.0276x over previous
#include <cuda_runtime.h>
#include <cuda_fp16.h>
#include <cuda_bf16.h>
#include <math_constants.h>
#include <cstdint>

// ---------------------------------------------------------------- constants
#define NROWS 16384   // B*H*W
#define NE    8192
#define EDIM  256
#define CH    256
#define HWSZ  1024
#define ZQ_ELEMS 4194304
#define LOSS_OFF 4194304
#define IDX_OFF  4194305
#define CAP   32      // shortlist capacity per row

// ---------------------------------------------------------------- scratch
__device__ float    g_zz[NROWS];
__device__ float    g_ee[NE];
__device__ int      g_idx[NROWS];
__device__ double   g_loss;
__device__ unsigned g_maxee;
__device__ unsigned g_rowmin[NROWS];        // order-mapped float
__device__ int      g_ccount[NROWS];
__device__ int      g_clist[NROWS][CAP];
__device__ float    g_Azf[NROWS * EDIM];    // z transposed, fp32 (for rescore)
__device__ uint16_t g_Abf[NROWS * EDIM];    // z transposed, bf16
__device__ uint16_t g_Bbf[NE * EDIM];       // codebook, bf16
__device__ uint16_t g_score[(size_t)NROWS * NE];  // fp16 scores, 256MB

// order-preserving float<->uint map (for atomicMin on floats of any sign)
__device__ __forceinline__ unsigned fmap(float f) {
    unsigned u = __float_as_uint(f);
    return (u & 0x80000000u) ? ~u : (u | 0x80000000u);
}
__device__ __forceinline__ float funmap(unsigned u) {
    u = (u & 0x80000000u) ? (u & 0x7FFFFFFFu) : ~u;
    return __uint_as_float(u);
}
__device__ __forceinline__ uint32_t smem_u32(const void* p) {
    uint32_t a;
    asm("{ .reg .u64 t; cvta.to.shared.u64 t, %1; cvt.u32.u64 %0, t; }" : "=r"(a) : "l"(p));
    return a;
}

// ---------------------------------------------------------------------------
__global__ void init_kernel() { g_maxee = 0; g_loss = 0.0; }

// prep: zz (ref rounding: unfused mul+add, ascending), ee (+ maxee),
//       reset rowmin/ccount
__global__ void prep_kernel(const float* __restrict__ z,
                            const float* __restrict__ cb) {
    int t = blockIdx.x * blockDim.x + threadIdx.x;
    if (t < NROWS) {
        g_rowmin[t] = 0xFFFFFFFFu;
        g_ccount[t] = 0;
        int b = t >> 10, hw = t & 1023;
        const float* p = z + (size_t)b * CH * HWSZ + hw;
        float s = 0.0f;
#pragma unroll 8
        for (int c = 0; c < CH; c++) {
            float v = p[c * HWSZ];
            s = __fadd_rn(s, __fmul_rn(v, v));
        }
        g_zz[t] = s;
    } else if (t < NROWS + NE) {
        int k = t - NROWS;
        const float* p = cb + (size_t)k * EDIM;
        float s = 0.0f;
#pragma unroll 8
        for (int d = 0; d < EDIM; d++) {
            float v = p[d];
            s = __fadd_rn(s, __fmul_rn(v, v));
        }
        g_ee[k] = s;
        atomicMax(&g_maxee, __float_as_uint(s));   // s >= 0: uint order ok
    }
}

// codebook -> bf16
__global__ void split_cb_kernel(const float* __restrict__ cb) {
    int i = blockIdx.x * blockDim.x + threadIdx.x;
    if (i < NE * EDIM) {
        __nv_bfloat16 h = __float2bfloat16_rn(cb[i]);
        g_Bbf[i] = *(uint16_t*)&h;
    }
}

// z: NCHW -> row-major [NROWS][EDIM], fp32 + bf16
__global__ void split_z_kernel(const float* __restrict__ z) {
    __shared__ float s[32][33];
    int b = blockIdx.z, c0 = blockIdx.y * 32, hw0 = blockIdx.x * 32;
    int tx = threadIdx.x, ty = threadIdx.y;   // block (32, 8)
    const float* zp = z + ((size_t)b * CH + c0) * HWSZ + hw0;
#pragma unroll
    for (int i = 0; i < 4; i++) {
        int cl = ty + i * 8;
        s[cl][tx] = zp[(size_t)cl * HWSZ + tx];
    }
    __syncthreads();
#pragma unroll
    for (int i = 0; i < 4; i++) {
        int hl = ty + i * 8;
        size_t o = (size_t)(b * HWSZ + hw0 + hl) * EDIM + c0 + tx;
        float x = s[tx][hl];
        g_Azf[o] = x;
        __nv_bfloat16 h = __float2bfloat16_rn(x);
        g_Abf[o] = *(uint16_t*)&h;
    }
}

// ---------------------------------------------------------------------------
// screening GEMM: bf16 mma.sync + ldmatrix, CTA 128 rows x 128 cands, K=256.
// 8 warps (wm 0..3) x (wn 0..1): warp tile 32x64.
// Smem tile: 128 rows x 32 bf16 (64B rows), 16B chunk swizzle c^( (r>>1)&3 )
// -> conflict-free for both STS.128 and ldmatrix 8-row phases.
// Emits fp16 score s = ee - 2*dot and per-row running min (atomics).
// ---------------------------------------------------------------------------
__global__ void __launch_bounds__(256, 2) screen_kernel() {
    __shared__ __align__(16) uint8_t sA[2][8192];   // 128 rows x 32 bf16
    __shared__ __align__(16) uint8_t sB[2][8192];
    __shared__ unsigned s_rmin[128];

    const int tid = threadIdx.x, lane = tid & 31, wid = tid >> 5;
    const int candTile = blockIdx.x & 63;
    const int rowTile  = blockIdx.x >> 6;
    const int row0 = rowTile * 128, cand0 = candTile * 128;
    const int wm = wid & 3, wn = wid >> 2;
    const int g = lane >> 2, tg = lane & 3;

    if (tid < 128) s_rmin[tid] = 0xFFFFFFFFu;

    // ---- per-lane ldmatrix address precompute
    const int rl  = lane & 7;
    const int sel = lane >> 3;            // which 8x8 matrix this lane addresses
    // A (x4 = rows{0-7,8-15} x chunks{c0,c1}): row += (sel&1)*8, chunk += sel>>1
    uint32_t aOff[2], aSw[2];
#pragma unroll
    for (int mf = 0; mf < 2; mf++) {
        int row = wm * 32 + mf * 16 + (sel & 1) * 8 + rl;
        aOff[mf] = (uint32_t)(row * 64);
        aSw[mf]  = (uint32_t)((row >> 1) & 3);
    }
    const uint32_t aCs = (uint32_t)(sel >> 1);
    // B (x4 = nf-pair rows{p*16+0-7, +8-15} x chunks): row += (sel>>1)*8, chunk += sel&1
    uint32_t bOff[4], bSw[4];
#pragma unroll
    for (int p = 0; p < 4; p++) {
        int row = wn * 64 + p * 16 + (sel >> 1) * 8 + rl;
        bOff[p] = (uint32_t)(row * 64);
        bSw[p]  = (uint32_t)((row >> 1) & 3);
    }
    const uint32_t bCs = (uint32_t)(sel & 1);
    const uint32_t smA = smem_u32(&sA[0][0]);
    const uint32_t smB = smem_u32(&sB[0][0]);

    float acc[2][8][4];
#pragma unroll
    for (int mf = 0; mf < 2; mf++)
#pragma unroll
        for (int nf = 0; nf < 8; nf++)
#pragma unroll
            for (int q = 0; q < 4; q++) acc[mf][nf][q] = 0.0f;

    uint4 pa[2], pb[2];

#define LDG_CHUNK(kc)                                                          \
    {                                                                          \
        _Pragma("unroll")                                                      \
        for (int it = 0; it < 2; it++) {                                       \
            int u = tid + it * 256, r = u >> 2, c = u & 3;                     \
            pa[it] = *(const uint4*)(g_Abf + (size_t)(row0 + r) * EDIM + (kc) * 32 + c * 8);  \
            pb[it] = *(const uint4*)(g_Bbf + (size_t)(cand0 + r) * EDIM + (kc) * 32 + c * 8); \
        }                                                                      \
    }
#define STS_CHUNK(buf)                                                         \
    {                                                                          \
        _Pragma("unroll")                                                      \
        for (int it = 0; it < 2; it++) {                                       \
            int u = tid + it * 256, r = u >> 2, c = u & 3;                     \
            int cs = c ^ ((r >> 1) & 3);                                       \
            *(uint4*)(sA[buf] + r * 64 + cs * 16) = pa[it];                    \
            *(uint4*)(sB[buf] + r * 64 + cs * 16) = pb[it];                    \
        }                                                                      \
    }
#define LDMX4(r0, r1, r2, r3, addr)                                            \
    asm volatile("ldmatrix.sync.aligned.m8n8.x4.shared.b16 {%0,%1,%2,%3}, [%4];" \
                 : "=r"(r0), "=r"(r1), "=r"(r2), "=r"(r3) : "r"(addr))

    LDG_CHUNK(0);
    STS_CHUNK(0);
    __syncthreads();

#pragma unroll 1
    for (int kc = 0; kc < 8; kc++) {
        if (kc < 7) LDG_CHUNK(kc + 1);
        const uint32_t bufA = smA + (uint32_t)(kc & 1) * 8192;
        const uint32_t bufB = smB + (uint32_t)(kc & 1) * 8192;
#pragma unroll
        for (int ks = 0; ks < 2; ks++) {
            uint32_t a[2][4], b[8][2];
            const uint32_t ca = (uint32_t)(2 * ks) + aCs;
            const uint32_t cbk = (uint32_t)(2 * ks) + bCs;
#pragma unroll
            for (int mf = 0; mf < 2; mf++) {
                uint32_t addr = bufA + aOff[mf] + (((ca ^ aSw[mf]) & 3u) << 4);
                LDMX4(a[mf][0], a[mf][1], a[mf][2], a[mf][3], addr);
            }
#pragma unroll
            for (int p = 0; p < 4; p++) {
                uint32_t addr = bufB + bOff[p] + (((cbk ^ bSw[p]) & 3u) << 4);
                LDMX4(b[2 * p][0], b[2 * p][1], b[2 * p + 1][0], b[2 * p + 1][1], addr);
            }
#pragma unroll
            for (int mf = 0; mf < 2; mf++)
#pragma unroll
                for (int nf = 0; nf < 8; nf++)
                    asm volatile(
                        "mma.sync.aligned.m16n8k16.row.col.f32.bf16.bf16.f32 "
                        "{%0,%1,%2,%3},{%4,%5,%6,%7},{%8,%9},{%0,%1,%2,%3};"
                        : "+f"(acc[mf][nf][0]), "+f"(acc[mf][nf][1]),
                          "+f"(acc[mf][nf][2]), "+f"(acc[mf][nf][3])
                        : "r"(a[mf][0]), "r"(a[mf][1]), "r"(a[mf][2]), "r"(a[mf][3]),
                          "r"(b[nf][0]), "r"(b[nf][1]));
        }
        if (kc < 7) {
            STS_CHUNK((kc + 1) & 1);
            __syncthreads();
        }
    }

    // epilogue: scores + per-row min
#pragma unroll
    for (int mf = 0; mf < 2; mf++)
#pragma unroll
        for (int h = 0; h < 2; h++) {
            int rl2 = wm * 32 + mf * 16 + g + h * 8;
            int row = row0 + rl2;
            float rmin = CUDART_INF_F;
#pragma unroll
            for (int nf = 0; nf < 8; nf++) {
                int cand = cand0 + wn * 64 + nf * 8 + 2 * tg;
                float s0 = __ldg(&g_ee[cand])     - 2.0f * acc[mf][nf][h * 2 + 0];
                float s1 = __ldg(&g_ee[cand + 1]) - 2.0f * acc[mf][nf][h * 2 + 1];
                __half2 hv = __floats2half2_rn(s0, s1);
                *(uint32_t*)&g_score[(size_t)row * NE + cand] = *(uint32_t*)&hv;
                rmin = fminf(rmin, fminf(s0, s1));
            }
            atomicMin(&s_rmin[rl2], fmap(rmin));
        }
    __syncthreads();
    if (tid < 128) atomicMin(&g_rowmin[row0 + tid], s_rmin[tid]);
}

// ---------------------------------------------------------------------------
// collect: one warp per row, gather candidates with score <= min + margin.
// margin >= 2*eps_screen (deterministic Cauchy-Schwarz bound) + fp16 slack.
// ---------------------------------------------------------------------------
__global__ void collect_kernel() {
    int w = (blockIdx.x * blockDim.x + threadIdx.x) >> 5;
    int lane = threadIdx.x & 31;
    if (w >= NROWS) return;
    float fmin = funmap(g_rowmin[w]);
    float marg = 0.024f * sqrtf(g_zz[w]) * sqrtf(__uint_as_float(g_maxee)) + 2e-5f;
    float thr = fmin + marg;
    const uint16_t* sp = g_score + (size_t)w * NE;
#pragma unroll 1
    for (int it = 0; it < 32; it++) {
        int cb0 = it * 256 + lane * 8;
        uint4 v = *(const uint4*)(sp + cb0);
        const __half2* hp = (const __half2*)&v;
#pragma unroll
        for (int q = 0; q < 4; q++) {
            float2 f2 = __half22float2(hp[q]);
            if (f2.x <= thr) {
                int p = atomicAdd(&g_ccount[w], 1);
                if (p < CAP) g_clist[w][p] = cb0 + q * 2;
            }
            if (f2.y <= thr) {
                int p = atomicAdd(&g_ccount[w], 1);
                if (p < CAP) g_clist[w][p] = cb0 + q * 2 + 1;
            }
        }
    }
}

// ---------------------------------------------------------------------------
// rescore: exact fp32 (ascending-d fmaf chain == R2) + reference rounding,
// lexicographic (d, idx) min -> first-index tie behavior. Warp per row.
// ---------------------------------------------------------------------------
__global__ void rescore_kernel(const float* __restrict__ cb) {
    int w = (blockIdx.x * blockDim.x + threadIdx.x) >> 5;
    int lane = threadIdx.x & 31;
    if (w >= NROWS) return;
    int cnt = g_ccount[w];
    float zzv = g_zz[w];
    const float* zr = g_Azf + (size_t)w * EDIM;
    float bd = CUDART_INF_F;
    int bi = 0x7FFFFFFF;
    if (cnt <= CAP) {
        if (lane < cnt) {
            int k = g_clist[w][lane];
            const float* er = cb + (size_t)k * EDIM;
            float s = 0.0f;
#pragma unroll 8
            for (int d = 0; d < EDIM; d++) s = fmaf(zr[d], er[d], s);
            float t = __fadd_rn(zzv, g_ee[k]);
            bd = __fadd_rn(t, -2.0f * s);
            bi = k;
        }
    } else {  // overflow (vanishingly rare): exact scan of all candidates
        for (int k = lane; k < NE; k += 32) {
            const float* er = cb + (size_t)k * EDIM;
            float s = 0.0f;
#pragma unroll 8
            for (int d = 0; d < EDIM; d++) s = fmaf(zr[d], er[d], s);
            float t = __fadd_rn(zzv, g_ee[k]);
            float dv = __fadd_rn(t, -2.0f * s);
            if (dv < bd || (dv == bd && k < bi)) { bd = dv; bi = k; }
        }
    }
#pragma unroll
    for (int o = 16; o; o >>= 1) {
        float od = __shfl_xor_sync(0xFFFFFFFFu, bd, o);
        int   oi = __shfl_xor_sync(0xFFFFFFFFu, bi, o);
        if (od < bd || (od == bd && oi < bi)) { bd = od; bi = oi; }
    }
    if (lane == 0) g_idx[w] = bi;
}

// ---------------------------------------------------------------------------
// output: z_q gather + loss partial sums
// ---------------------------------------------------------------------------
__global__ void output_kernel(const float* __restrict__ z,
                              const float* __restrict__ cb,
                              float* __restrict__ out) {
    float lsum = 0.0f;
    int stride = gridDim.x * blockDim.x;
    for (int o = blockIdx.x * blockDim.x + threadIdx.x; o < ZQ_ELEMS; o += stride) {
        int bq = o >> 18;
        int c  = (o >> 10) & 255;
        int hw = o & 1023;
        int n  = (bq << 10) | hw;
        int id = g_idx[n];
        float q  = __ldg(&cb[(size_t)id * EDIM + c]);
        float zp = z[o];
        out[o] = q;
        float dd = q - zp;
        lsum += dd * dd;
    }
    __shared__ float red[256];
    red[threadIdx.x] = lsum;
    __syncthreads();
    for (int s = 128; s > 0; s >>= 1) {
        if (threadIdx.x < s) red[threadIdx.x] += red[threadIdx.x + s];
        __syncthreads();
    }
    if (threadIdx.x == 0) atomicAdd(&g_loss, (double)red[0]);
}

__global__ void finalize_kernel(float* __restrict__ out, int out_size) {
    int t = blockIdx.x * blockDim.x + threadIdx.x;
    if (t == 0 && out_size > LOSS_OFF) {
        float m = (float)(g_loss * (1.0 / 4194304.0));
        out[LOSS_OFF] = __fadd_rn(m, 0.25f * m);
    }
    if (t < NROWS && out_size >= IDX_OFF + NROWS) {
        out[IDX_OFF + t] = (float)g_idx[t];
    }
}

// ---------------------------------------------------------------------------
extern "C" void kernel_launch(void* const* d_in, const int* in_sizes, int n_in,
                              void* d_out, int out_size) {
    const float* z  = (const float*)d_in[0];
    const float* cb = (const float*)d_in[1];
    float* out = (float*)d_out;

    init_kernel<<<1, 1>>>();
    prep_kernel<<<(NROWS + NE + 255) / 256, 256>>>(z, cb);
    split_cb_kernel<<<(NE * EDIM) / 256, 256>>>(cb);
    split_z_kernel<<<dim3(HWSZ / 32, CH / 32, 16), dim3(32, 8)>>>(z);
    screen_kernel<<<128 * 64, 256>>>();
    collect_kernel<<<(NROWS * 32) / 256, 256>>>();
    rescore_kernel<<<(NROWS * 32) / 256, 256>>>(cb);
    output_kernel<<<1024, 256>>>(z, cb, out);
    finalize_kernel<<<(NROWS + 255) / 256, 256>>>(out, out_size);
}

// round 8
// speedup vs baseline: 3.9280x; 1.0468x over previous
#include <cuda_runtime.h>
#include <cuda_fp16.h>
#include <cuda_bf16.h>
#include <math_constants.h>
#include <cstdint>

// ---------------------------------------------------------------- constants
#define NROWS 16384   // B*H*W
#define NE    8192
#define EDIM  256
#define CH    256
#define HWSZ  1024
#define ZQ_ELEMS 4194304
#define LOSS_OFF 4194304
#define IDX_OFF  4194305
#define CAP   64      // shortlist capacity per row

#define SCREEN_SMEM 99840

// ---------------------------------------------------------------- scratch
__device__ float    g_zz[NROWS];
__device__ float    g_ee[NE];
__device__ int      g_idx[NROWS];
__device__ double   g_loss;
__device__ unsigned g_maxee;
__device__ unsigned g_rowmin[NROWS];        // order-mapped float
__device__ int      g_ccount[NROWS];
__device__ int      g_clist[NROWS][CAP];
__device__ float    g_Azf[NROWS * EDIM];    // z transposed, fp32 (for rescore)
__device__ uint16_t g_Abf[NROWS * EDIM];    // z transposed, bf16
__device__ uint16_t g_Bbf[NE * EDIM];       // codebook, bf16

// order-preserving float<->uint map (for atomicMin on floats of any sign)
__device__ __forceinline__ unsigned fmap(float f) {
    unsigned u = __float_as_uint(f);
    return (u & 0x80000000u) ? ~u : (u | 0x80000000u);
}
__device__ __forceinline__ float funmap(unsigned u) {
    u = (u & 0x80000000u) ? (u & 0x7FFFFFFFu) : ~u;
    return __uint_as_float(u);
}
__device__ __forceinline__ uint32_t smem_u32(const void* p) {
    uint32_t a;
    asm("{ .reg .u64 t; cvta.to.shared.u64 t, %1; cvt.u32.u64 %0, t; }" : "=r"(a) : "l"(p));
    return a;
}

// ---------------------------------------------------------------------------
__global__ void init_kernel() { g_maxee = 0; g_loss = 0.0; }

// prep: zz (ref rounding: unfused mul+add, ascending), ee (+ maxee),
//       reset rowmin/ccount
__global__ void prep_kernel(const float* __restrict__ z,
                            const float* __restrict__ cb) {
    int t = blockIdx.x * blockDim.x + threadIdx.x;
    if (t < NROWS) {
        g_rowmin[t] = 0xFFFFFFFFu;
        g_ccount[t] = 0;
        int b = t >> 10, hw = t & 1023;
        const float* p = z + (size_t)b * CH * HWSZ + hw;
        float s = 0.0f;
#pragma unroll 8
        for (int c = 0; c < CH; c++) {
            float v = p[c * HWSZ];
            s = __fadd_rn(s, __fmul_rn(v, v));
        }
        g_zz[t] = s;
    } else if (t < NROWS + NE) {
        int k = t - NROWS;
        const float* p = cb + (size_t)k * EDIM;
        float s = 0.0f;
#pragma unroll 8
        for (int d = 0; d < EDIM; d++) {
            float v = p[d];
            s = __fadd_rn(s, __fmul_rn(v, v));
        }
        g_ee[k] = s;
        atomicMax(&g_maxee, __float_as_uint(s));   // s >= 0: uint order ok
    }
}

// codebook -> bf16
__global__ void split_cb_kernel(const float* __restrict__ cb) {
    int i = blockIdx.x * blockDim.x + threadIdx.x;
    if (i < NE * EDIM) {
        __nv_bfloat16 h = __float2bfloat16_rn(cb[i]);
        g_Bbf[i] = *(uint16_t*)&h;
    }
}

// z: NCHW -> row-major [NROWS][EDIM], fp32 + bf16
__global__ void split_z_kernel(const float* __restrict__ z) {
    __shared__ float s[32][33];
    int b = blockIdx.z, c0 = blockIdx.y * 32, hw0 = blockIdx.x * 32;
    int tx = threadIdx.x, ty = threadIdx.y;   // block (32, 8)
    const float* zp = z + ((size_t)b * CH + c0) * HWSZ + hw0;
#pragma unroll
    for (int i = 0; i < 4; i++) {
        int cl = ty + i * 8;
        s[cl][tx] = zp[(size_t)cl * HWSZ + tx];
    }
    __syncthreads();
#pragma unroll
    for (int i = 0; i < 4; i++) {
        int hl = ty + i * 8;
        size_t o = (size_t)(b * HWSZ + hw0 + hl) * EDIM + c0 + tx;
        float x = s[tx][hl];
        g_Azf[o] = x;
        __nv_bfloat16 h = __float2bfloat16_rn(x);
        g_Abf[o] = *(uint16_t*)&h;
    }
}

// ---------------------------------------------------------------------------
// screening GEMM: bf16 mma.sync + ldmatrix + cp.async 3-stage pipeline.
// CTA 128 rows x 128 cands, K=256 in 4 chunks of 64. No score materialization:
// epilogue computes per-row block min, folds into global running atomicMin,
// then appends candidates within (running_min + margin) to g_clist.
// Sound: true winner <= any running min -> always appended (margin >= 2*eps).
// Smem row = 64 bf16 = 128B; 16B-chunk swizzle c ^ (r&7): conflict-free for
// cp.async stores and ldmatrix 8-row phases.
// ---------------------------------------------------------------------------
extern __shared__ __align__(16) uint8_t dsmem[];

#define CP_ASYNC(dst, src) \
    asm volatile("cp.async.cg.shared.global [%0], [%1], 16;" :: "r"(dst), "l"(src) : "memory")
#define CP_COMMIT() asm volatile("cp.async.commit_group;" ::: "memory")
#define CP_WAIT(n)  asm volatile("cp.async.wait_group %0;" :: "n"(n) : "memory")
#define LDMX4(r0, r1, r2, r3, addr)                                            \
    asm volatile("ldmatrix.sync.aligned.m8n8.x4.shared.b16 {%0,%1,%2,%3}, [%4];" \
                 : "=r"(r0), "=r"(r1), "=r"(r2), "=r"(r3) : "r"(addr))

__global__ void __launch_bounds__(256, 2) screen_kernel() {
    const int tid = threadIdx.x, lane = tid & 31, wid = tid >> 5;
    const int rowTile  = blockIdx.x & 127;   // fast-varying: first wave covers all rows
    const int candTile = blockIdx.x >> 7;
    const int row0 = rowTile * 128, cand0 = candTile * 128;
    const int wm = wid & 3, wn = wid >> 2;
    const int g = lane >> 2, tg = lane & 3;

    uint8_t*  sAp    = dsmem;                      // 3 stages x 16KB
    uint8_t*  sBp    = dsmem + 49152;              // 3 stages x 16KB
    unsigned* s_rmin = (unsigned*)(dsmem + 98304);
    float*    s_thr  = (float*)(dsmem + 98816);
    float*    s_ee   = (float*)(dsmem + 99328);
    const uint32_t smA = smem_u32(sAp);
    const uint32_t smB = smem_u32(sBp);

    if (tid < 128) {
        s_rmin[tid] = 0xFFFFFFFFu;
        s_ee[tid]   = g_ee[cand0 + tid];
    }

    // ---- per-lane ldmatrix address precompute
    const int rl  = lane & 7;
    const int sel = lane >> 3;
    uint32_t aOff[2]; uint32_t aM7[2];
#pragma unroll
    for (int mf = 0; mf < 2; mf++) {
        int row = wm * 32 + mf * 16 + (sel & 1) * 8 + rl;
        aOff[mf] = (uint32_t)(row * 128);
        aM7[mf]  = (uint32_t)(row & 7);
    }
    const uint32_t aCs = (uint32_t)(sel >> 1);
    uint32_t bOff[4]; uint32_t bM7[4];
#pragma unroll
    for (int p = 0; p < 4; p++) {
        int row = wn * 64 + p * 16 + (sel >> 1) * 8 + rl;
        bOff[p] = (uint32_t)(row * 128);
        bM7[p]  = (uint32_t)(row & 7);
    }
    const uint32_t bCs = (uint32_t)(sel & 1);

    float acc[2][8][4];
#pragma unroll
    for (int mf = 0; mf < 2; mf++)
#pragma unroll
        for (int nf = 0; nf < 8; nf++)
#pragma unroll
            for (int q = 0; q < 4; q++) acc[mf][nf][q] = 0.0f;

#define LOAD_CHUNK(stage, kc)                                                  \
    {                                                                          \
        _Pragma("unroll")                                                      \
        for (int it = 0; it < 4; it++) {                                       \
            int u = tid + it * 256;                                            \
            int r = u >> 3, c = u & 7;                                         \
            uint32_t so = (uint32_t)((stage) * 16384 + r * 128 + ((c ^ (r & 7)) << 4)); \
            CP_ASYNC(smA + so, g_Abf + (size_t)(row0 + r) * EDIM + (kc) * 64 + c * 8);  \
            CP_ASYNC(smB + so, g_Bbf + (size_t)(cand0 + r) * EDIM + (kc) * 64 + c * 8); \
        }                                                                      \
        CP_COMMIT();                                                           \
    }

#define MMA_CHUNK(stage)                                                       \
    {                                                                          \
        const uint32_t bufA = smA + (stage) * 16384;                           \
        const uint32_t bufB = smB + (stage) * 16384;                           \
        _Pragma("unroll")                                                      \
        for (int ks = 0; ks < 4; ks++) {                                       \
            uint32_t a[2][4], b[8][2];                                         \
            const uint32_t ca  = (uint32_t)(2 * ks) + aCs;                     \
            const uint32_t cbk = (uint32_t)(2 * ks) + bCs;                     \
            _Pragma("unroll")                                                  \
            for (int mf = 0; mf < 2; mf++) {                                   \
                uint32_t addr = bufA + aOff[mf] + (((ca ^ aM7[mf]) & 7u) << 4); \
                LDMX4(a[mf][0], a[mf][1], a[mf][2], a[mf][3], addr);           \
            }                                                                  \
            _Pragma("unroll")                                                  \
            for (int p = 0; p < 4; p++) {                                      \
                uint32_t addr = bufB + bOff[p] + (((cbk ^ bM7[p]) & 7u) << 4); \
                LDMX4(b[2*p][0], b[2*p][1], b[2*p+1][0], b[2*p+1][1], addr);   \
            }                                                                  \
            _Pragma("unroll")                                                  \
            for (int mf = 0; mf < 2; mf++)                                     \
                _Pragma("unroll")                                              \
                for (int nf = 0; nf < 8; nf++)                                 \
                    asm volatile(                                              \
                        "mma.sync.aligned.m16n8k16.row.col.f32.bf16.bf16.f32 " \
                        "{%0,%1,%2,%3},{%4,%5,%6,%7},{%8,%9},{%0,%1,%2,%3};"   \
                        : "+f"(acc[mf][nf][0]), "+f"(acc[mf][nf][1]),          \
                          "+f"(acc[mf][nf][2]), "+f"(acc[mf][nf][3])           \
                        : "r"(a[mf][0]), "r"(a[mf][1]), "r"(a[mf][2]), "r"(a[mf][3]), \
                          "r"(b[nf][0]), "r"(b[nf][1]));                       \
        }                                                                      \
    }

    // 3-stage pipeline over 4 K-chunks
    LOAD_CHUNK(0, 0);
    LOAD_CHUNK(1, 1);
    LOAD_CHUNK(2, 2);

    CP_WAIT(2); __syncthreads();      // chunk 0 ready
    MMA_CHUNK(0);
    __syncthreads();                  // stage 0 free
    LOAD_CHUNK(0, 3);

    CP_WAIT(2); __syncthreads();      // chunk 1 ready
    MMA_CHUNK(1);

    CP_WAIT(1); __syncthreads();      // chunk 2 ready
    MMA_CHUNK(2);

    CP_WAIT(0); __syncthreads();      // chunk 3 ready (in stage 0)
    MMA_CHUNK(0);

    // ---- epilogue pass 1: per-row block min
#pragma unroll
    for (int mf = 0; mf < 2; mf++)
#pragma unroll
        for (int h = 0; h < 2; h++) {
            int rlo = wm * 32 + mf * 16 + g + h * 8;
            float rmin = CUDART_INF_F;
#pragma unroll
            for (int nf = 0; nf < 8; nf++) {
                int cl = wn * 64 + nf * 8 + 2 * tg;
                float s0 = s_ee[cl]     - 2.0f * acc[mf][nf][h * 2 + 0];
                float s1 = s_ee[cl + 1] - 2.0f * acc[mf][nf][h * 2 + 1];
                rmin = fminf(rmin, fminf(s0, s1));
            }
            atomicMin(&s_rmin[rlo], fmap(rmin));
        }
    __syncthreads();
    // fold into global running min, compute threshold
    if (tid < 128) {
        unsigned mine = s_rmin[tid];
        unsigned old  = atomicMin(&g_rowmin[row0 + tid], mine);
        float gmin = fminf(funmap(old), funmap(mine));
        float sqee = sqrtf(__uint_as_float(g_maxee));
        s_thr[tid] = gmin + 0.024f * sqrtf(g_zz[row0 + tid]) * sqee + 2e-5f;
    }
    __syncthreads();
    // ---- epilogue pass 2: append candidates under threshold
#pragma unroll
    for (int mf = 0; mf < 2; mf++)
#pragma unroll
        for (int h = 0; h < 2; h++) {
            int rlo = wm * 32 + mf * 16 + g + h * 8;
            int grow = row0 + rlo;
            float thr = s_thr[rlo];
#pragma unroll
            for (int nf = 0; nf < 8; nf++) {
                int cl = wn * 64 + nf * 8 + 2 * tg;
                float s0 = s_ee[cl]     - 2.0f * acc[mf][nf][h * 2 + 0];
                float s1 = s_ee[cl + 1] - 2.0f * acc[mf][nf][h * 2 + 1];
                if (s0 <= thr) {
                    int p = atomicAdd(&g_ccount[grow], 1);
                    if (p < CAP) g_clist[grow][p] = cand0 + cl;
                }
                if (s1 <= thr) {
                    int p = atomicAdd(&g_ccount[grow], 1);
                    if (p < CAP) g_clist[grow][p] = cand0 + cl + 1;
                }
            }
        }
}

// ---------------------------------------------------------------------------
// rescore: exact fp32 (ascending-d fmaf chain) + reference rounding,
// lexicographic (d, idx) min -> first-index tie behavior. Warp per row.
// ---------------------------------------------------------------------------
__global__ void rescore_kernel(const float* __restrict__ cb) {
    int w = (blockIdx.x * blockDim.x + threadIdx.x) >> 5;
    int lane = threadIdx.x & 31;
    if (w >= NROWS) return;
    int cnt = g_ccount[w];
    float zzv = g_zz[w];
    const float* zr = g_Azf + (size_t)w * EDIM;
    float bd = CUDART_INF_F;
    int bi = 0x7FFFFFFF;
    if (cnt <= CAP) {
        for (int sl = lane; sl < cnt; sl += 32) {
            int k = g_clist[w][sl];
            const float* er = cb + (size_t)k * EDIM;
            float s = 0.0f;
#pragma unroll 8
            for (int d = 0; d < EDIM; d++) s = fmaf(zr[d], er[d], s);
            float t = __fadd_rn(zzv, g_ee[k]);
            float dv = __fadd_rn(t, -2.0f * s);
            if (dv < bd || (dv == bd && k < bi)) { bd = dv; bi = k; }
        }
    } else {  // overflow (rare): exact scan of all candidates
        for (int k = lane; k < NE; k += 32) {
            const float* er = cb + (size_t)k * EDIM;
            float s = 0.0f;
#pragma unroll 8
            for (int d = 0; d < EDIM; d++) s = fmaf(zr[d], er[d], s);
            float t = __fadd_rn(zzv, g_ee[k]);
            float dv = __fadd_rn(t, -2.0f * s);
            if (dv < bd || (dv == bd && k < bi)) { bd = dv; bi = k; }
        }
    }
#pragma unroll
    for (int o = 16; o; o >>= 1) {
        float od = __shfl_xor_sync(0xFFFFFFFFu, bd, o);
        int   oi = __shfl_xor_sync(0xFFFFFFFFu, bi, o);
        if (od < bd || (od == bd && oi < bi)) { bd = od; bi = oi; }
    }
    if (lane == 0) g_idx[w] = bi;
}

// ---------------------------------------------------------------------------
// output: z_q gather + loss partial sums
// ---------------------------------------------------------------------------
__global__ void output_kernel(const float* __restrict__ z,
                              const float* __restrict__ cb,
                              float* __restrict__ out) {
    float lsum = 0.0f;
    int stride = gridDim.x * blockDim.x;
    for (int o = blockIdx.x * blockDim.x + threadIdx.x; o < ZQ_ELEMS; o += stride) {
        int bq = o >> 18;
        int c  = (o >> 10) & 255;
        int hw = o & 1023;
        int n  = (bq << 10) | hw;
        int id = g_idx[n];
        float q  = __ldg(&cb[(size_t)id * EDIM + c]);
        float zp = z[o];
        out[o] = q;
        float dd = q - zp;
        lsum += dd * dd;
    }
    __shared__ float red[256];
    red[threadIdx.x] = lsum;
    __syncthreads();
    for (int s = 128; s > 0; s >>= 1) {
        if (threadIdx.x < s) red[threadIdx.x] += red[threadIdx.x + s];
        __syncthreads();
    }
    if (threadIdx.x == 0) atomicAdd(&g_loss, (double)red[0]);
}

__global__ void finalize_kernel(float* __restrict__ out, int out_size) {
    int t = blockIdx.x * blockDim.x + threadIdx.x;
    if (t == 0 && out_size > LOSS_OFF) {
        float m = (float)(g_loss * (1.0 / 4194304.0));
        out[LOSS_OFF] = __fadd_rn(m, 0.25f * m);
    }
    if (t < NROWS && out_size >= IDX_OFF + NROWS) {
        out[IDX_OFF + t] = (float)g_idx[t];
    }
}

// ---------------------------------------------------------------------------
extern "C" void kernel_launch(void* const* d_in, const int* in_sizes, int n_in,
                              void* d_out, int out_size) {
    const float* z  = (const float*)d_in[0];
    const float* cb = (const float*)d_in[1];
    float* out = (float*)d_out;

    cudaFuncSetAttribute(screen_kernel,
                         cudaFuncAttributeMaxDynamicSharedMemorySize, SCREEN_SMEM);

    init_kernel<<<1, 1>>>();
    prep_kernel<<<(NROWS + NE + 255) / 256, 256>>>(z, cb);
    split_cb_kernel<<<(NE * EDIM) / 256, 256>>>(cb);
    split_z_kernel<<<dim3(HWSZ / 32, CH / 32, 16), dim3(32, 8)>>>(z);
    screen_kernel<<<128 * 64, 256, SCREEN_SMEM>>>();
    rescore_kernel<<<(NROWS * 32) / 256, 256>>>(cb);
    output_kernel<<<1024, 256>>>(z, cb, out);
    finalize_kernel<<<(NROWS + 255) / 256, 256>>>(out, out_size);
}